// round 3
// baseline (speedup 1.0000x reference)
#include <cuda_runtime.h>
#include <math.h>

#define BB 512
#define DD 512
#define LL 24

#define TM 128
#define TN 64
#define KC 16
#define SPLITS 4
#define KSP (DD / SPLITS)   // 128
#define NBLK 128            // 8 col-tiles x 4 row-tiles x 4 splits

// Scratch (device globals — no allocations allowed)
__device__ float             g_part[SPLITS][BB * BB];
__device__ float             g_npart[SPLITS][BB];
__device__ unsigned int      g_lab[BB];
__device__ float             g_sum;
__device__ unsigned int      g_cnt;
__device__ unsigned int      g_done;
__device__ volatile unsigned g_bar;

// ---------------------------------------------------------------------------
// Single fused kernel: Gram partials -> grid spin-barrier -> triplet + final.
// 128 blocks x 256 threads: <= 1 block/SM, all co-resident => spin is safe.
// ---------------------------------------------------------------------------
__global__ __launch_bounds__(256) void k_fused(const float* __restrict__ X,
                                               const int* __restrict__ labels,
                                               float* __restrict__ out) {
    __shared__ float    As[KC][TM + 4];
    __shared__ float    Bs[KC][TN + 4];
    __shared__ float    norms[BB];
    __shared__ unsigned labs[BB];
    __shared__ float    nd[BB];
    __shared__ int      nn;
    __shared__ float    wsum[8];
    __shared__ unsigned wcnt[8];

    int tid = threadIdx.x;
    int wu  = blockIdx.x;
    int bx  = wu & 7;           // 8 column tiles of 64
    int by  = (wu >> 3) & 3;    // 4 row tiles of 128
    int z   = wu >> 5;          // 4 K-splits

    // side-duty: pack label bitmasks (block 0, before the barrier)
    if (wu == 0) {
        for (int i2 = tid; i2 < BB; i2 += 256) {
            unsigned m = 0u;
#pragma unroll
            for (int l = 0; l < LL; ++l)
                if (labels[i2 * LL + l] != 0) m |= (1u << l);
            g_lab[i2] = m;
        }
    }

    // ---------------- Phase 1: Gram partial tile (128x64, K-split) ----------
    int rowBase = by * TM;
    int colBase = bx * TN;
    int kBase   = z * KSP;
    int tx = tid & 15;          // 16 col-groups of 4
    int ty = tid >> 4;          // 16 row-groups of 8

    float acc[8][4] = {};

    for (int k0 = 0; k0 < KSP; k0 += KC) {
#pragma unroll
        for (int s = 0; s < 2; ++s) {
            int idx = tid + s * 256;
            int r   = idx >> 2;
            int kg  = (idx & 3) * 4;
            float4 v = *reinterpret_cast<const float4*>(
                &X[(rowBase + r) * DD + kBase + k0 + kg]);
            As[kg + 0][r] = v.x; As[kg + 1][r] = v.y;
            As[kg + 2][r] = v.z; As[kg + 3][r] = v.w;
        }
        {
            int r  = tid >> 2;
            int kg = (tid & 3) * 4;
            float4 v = *reinterpret_cast<const float4*>(
                &X[(colBase + r) * DD + kBase + k0 + kg]);
            Bs[kg + 0][r] = v.x; Bs[kg + 1][r] = v.y;
            Bs[kg + 2][r] = v.z; Bs[kg + 3][r] = v.w;
        }
        __syncthreads();

#pragma unroll
        for (int kk = 0; kk < KC; ++kk) {
            float4 a0 = *reinterpret_cast<const float4*>(&As[kk][ty * 8]);
            float4 a1 = *reinterpret_cast<const float4*>(&As[kk][ty * 8 + 4]);
            float4 b4 = *reinterpret_cast<const float4*>(&Bs[kk][tx * 4]);
            float av[8] = {a0.x, a0.y, a0.z, a0.w, a1.x, a1.y, a1.z, a1.w};
            float bv[4] = {b4.x, b4.y, b4.z, b4.w};
#pragma unroll
            for (int u = 0; u < 8; ++u)
#pragma unroll
                for (int v = 0; v < 4; ++v)
                    acc[u][v] = fmaf(av[u], bv[v], acc[u][v]);
        }
        __syncthreads();
    }

#pragma unroll
    for (int u = 0; u < 8; ++u) {
        int gi = rowBase + ty * 8 + u;
        int gj = colBase + tx * 4;
        *reinterpret_cast<float4*>(&g_part[z][gi * BB + gj]) =
            make_float4(acc[u][0], acc[u][1], acc[u][2], acc[u][3]);
        int dj = gi - gj;
        if ((unsigned)dj < 4u) g_npart[z][gi] = acc[u][dj];
    }

    // ---------------- Grid barrier (all 128 blocks co-resident) -------------
    __threadfence();
    __syncthreads();
    if (tid == 0) {
        atomicAdd((unsigned*)&g_bar, 1u);
        while (g_bar < NBLK) { }
    }
    __syncthreads();

    // ---------------- Phase 2: triplets for 4 anchors per block -------------
    for (int t = tid; t < BB; t += 256) {
        norms[t] = ((g_npart[0][t] + g_npart[1][t]) + g_npart[2][t]) + g_npart[3][t];
        labs[t]  = g_lab[t];
    }
    __syncthreads();

    float    lsum = 0.0f;
    unsigned lcnt = 0u;

    for (int a = 0; a < 4; ++a) {
        int i = blockIdx.x * 4 + a;
        unsigned mi = labs[i];
        float    ni = norms[i];
        if (tid == 0) nn = 0;
        __syncthreads();

        float djv[2];
        int   posf[2];
#pragma unroll
        for (int s = 0; s < 2; ++s) {
            int j = tid + s * 256;
            const float* p = &g_part[0][i * BB + j];
            float G  = ((p[0] + p[BB * BB]) + p[2 * BB * BB]) + p[3 * BB * BB];
            float sq = ni + norms[j] - 2.0f * G;
            float d  = (sq > 0.0f) ? sqrtf(sq) : 0.0f;
            int  pos = (labs[j] & mi) != 0u;
            djv[s]  = d;
            posf[s] = pos;
            if (!pos) nd[atomicAdd(&nn, 1)] = d;   // negatives are rare
        }
        __syncthreads();

        int N = nn;
        if (N > 0) {
#pragma unroll
            for (int s = 0; s < 2; ++s) {
                if (posf[s]) {
                    float dj_ = djv[s];
                    for (int k = 0; k < N; ++k) {
                        float v = dj_ - nd[k];
                        if (v > 1e-16f) { lsum += v; lcnt++; }
                    }
                }
            }
        }
        __syncthreads();
    }

    // ---------------- Block reduction + global accumulate + finalize --------
#pragma unroll
    for (int off = 16; off; off >>= 1) {
        lsum += __shfl_down_sync(0xffffffffu, lsum, off);
        lcnt += __shfl_down_sync(0xffffffffu, lcnt, off);
    }
    int lane = tid & 31, wid = tid >> 5;
    if (lane == 0) { wsum[wid] = lsum; wcnt[wid] = lcnt; }
    __syncthreads();
    if (wid == 0) {
        lsum = (lane < 8) ? wsum[lane] : 0.0f;
        lcnt = (lane < 8) ? wcnt[lane] : 0u;
#pragma unroll
        for (int off = 4; off; off >>= 1) {
            lsum += __shfl_down_sync(0xffffffffu, lsum, off);
            lcnt += __shfl_down_sync(0xffffffffu, lcnt, off);
        }
        if (lane == 0) {
            if (lcnt != 0u || lsum != 0.0f) {
                atomicAdd(&g_sum, lsum);
                atomicAdd(&g_cnt, lcnt);
            }
            __threadfence();
            unsigned prev = atomicAdd(&g_done, 1u);
            if (prev == NBLK - 1) {
                float    s = *((volatile float*)&g_sum);
                unsigned c = *((volatile unsigned*)&g_cnt);
                out[0] = (float)((double)s / ((double)c + 1e-16));
                // reset for the next (graph-replayed) launch
                g_sum  = 0.0f;
                g_cnt  = 0u;
                g_done = 0u;
                g_bar  = 0u;
            }
        }
    }
}

extern "C" void kernel_launch(void* const* d_in, const int* in_sizes, int n_in,
                              void* d_out, int out_size) {
    const float* src = (const float*)d_in[0];  // (B, D) float32
    const int*   lab = (const int*)d_in[1];    // (B, L) int32

    k_fused<<<NBLK, 256>>>(src, lab, (float*)d_out);
}

// round 5
// speedup vs baseline: 1.0863x; 1.0863x over previous
#include <cuda_runtime.h>
#include <math.h>
#include <stdint.h>

#define BB 512
#define DD 512
#define LL 24

#define TILE 64
#define KC   16
#define SPLITS 2
#define KSP (DD / SPLITS)   // 256
#define NTRI 128

// Scratch (device globals — no allocations allowed)
__device__ float        g_part[SPLITS][BB * BB];   // Gram partials per K-split
__device__ float        g_npart[SPLITS][BB];       // diagonal (norm) partials
__device__ unsigned int g_lab[BB];
__device__ float        g_sum;
__device__ unsigned int g_cnt;
__device__ unsigned int g_done;

// Packed dual-FP32 FMA (Blackwell f32x2 path; base-family PTX, sm_100+)
#define FMA2(acc, a, b) \
    asm("fma.rn.f32x2 %0, %1, %2, %0;" : "+l"(acc) : "l"(a), "l"(b))
#define PACK_DUP(out, f) \
    asm("mov.b64 %0, {%1, %1};" : "=l"(out) : "r"(__float_as_uint(f)))
#define UNPACK2(lo, hi, in) \
    asm("mov.b64 {%0, %1}, %2;" : "=r"(lo), "=r"(hi) : "l"(in))

// ---------------------------------------------------------------------------
// Kernel 1: Gram partials via packed FFMA2. 64x64 tile, K-split over z.
// Thread microtile: 8 rows (4 row-pairs) x 2 cols. 256 threads = 8 x 32.
// Block (0,0,0) packs label bitmasks and resets accumulators.
// ---------------------------------------------------------------------------
__global__ __launch_bounds__(256) void k_gram(const float* __restrict__ X,
                                              const int* __restrict__ labels) {
    __shared__ float As[KC][TILE + 4];   // K-major, row stride 68 floats (16B-aligned)
    __shared__ float Bs[KC][TILE + 4];

    int tid = threadIdx.x;

    if (blockIdx.x == 0 && blockIdx.y == 0 && blockIdx.z == 0) {
        for (int i = tid; i < BB; i += 256) {
            unsigned m = 0u;
#pragma unroll
            for (int l = 0; l < LL; ++l)
                if (labels[i * LL + l] != 0) m |= (1u << l);
            g_lab[i] = m;
        }
        if (tid == 0) { g_sum = 0.0f; g_cnt = 0u; g_done = 0u; }
    }

    int ty = tid >> 5;          // 0..7  : row-group of 8 rows (4 pairs)
    int tx = tid & 31;          // 0..31 : col-group of 2 cols
    int rowBase = blockIdx.y * TILE;
    int colBase = blockIdx.x * TILE;
    int z       = blockIdx.z;
    int kBase   = z * KSP;

    unsigned long long acc[4][2];
#pragma unroll
    for (int p = 0; p < 4; ++p) { acc[p][0] = 0ull; acc[p][1] = 0ull; }

    for (int k0 = 0; k0 < KSP; k0 += KC) {
        // stage A,B tiles K-major: 64 rows x 16 k each = 256 float4 per tile
        {
            int r  = tid >> 2;             // 0..63
            int kg = (tid & 3) * 4;        // 0,4,8,12
            float4 va = *reinterpret_cast<const float4*>(
                &X[(rowBase + r) * DD + kBase + k0 + kg]);
            As[kg + 0][r] = va.x; As[kg + 1][r] = va.y;
            As[kg + 2][r] = va.z; As[kg + 3][r] = va.w;
            float4 vb = *reinterpret_cast<const float4*>(
                &X[(colBase + r) * DD + kBase + k0 + kg]);
            Bs[kg + 0][r] = vb.x; Bs[kg + 1][r] = vb.y;
            Bs[kg + 2][r] = vb.z; Bs[kg + 3][r] = vb.w;
        }
        __syncthreads();

#pragma unroll
        for (int kk = 0; kk < KC; ++kk) {
            // 4 row-pairs as u64 (two LDS.128, warp-broadcast)
            const ulonglong2* ap =
                reinterpret_cast<const ulonglong2*>(&As[kk][ty * 8]);
            ulonglong2 a01 = ap[0];        // pairs (r0,r1) (r2,r3)
            ulonglong2 a23 = ap[1];        // pairs (r4,r5) (r6,r7)
            float b0 = Bs[kk][tx * 2 + 0];
            float b1 = Bs[kk][tx * 2 + 1];
            unsigned long long B0, B1;
            PACK_DUP(B0, b0);
            PACK_DUP(B1, b1);
            FMA2(acc[0][0], a01.x, B0);  FMA2(acc[0][1], a01.x, B1);
            FMA2(acc[1][0], a01.y, B0);  FMA2(acc[1][1], a01.y, B1);
            FMA2(acc[2][0], a23.x, B0);  FMA2(acc[2][1], a23.x, B1);
            FMA2(acc[3][0], a23.y, B0);  FMA2(acc[3][1], a23.y, B1);
        }
        __syncthreads();
    }

    // epilogue: unpack pairs, store partial tile + diagonal partials
    int gj = colBase + tx * 2;
#pragma unroll
    for (int p = 0; p < 4; ++p) {
        unsigned lo0, hi0, lo1, hi1;
        UNPACK2(lo0, hi0, acc[p][0]);    // col gj   : rows (2p, 2p+1)
        UNPACK2(lo1, hi1, acc[p][1]);    // col gj+1 : rows (2p, 2p+1)
        int gi0 = rowBase + ty * 8 + p * 2;
        float2 r0 = make_float2(__uint_as_float(lo0), __uint_as_float(lo1));
        float2 r1 = make_float2(__uint_as_float(hi0), __uint_as_float(hi1));
        *reinterpret_cast<float2*>(&g_part[z][gi0 * BB + gj])       = r0;
        *reinterpret_cast<float2*>(&g_part[z][(gi0 + 1) * BB + gj]) = r1;
        int d0 = gi0 - gj;
        if (d0 == 0) g_npart[z][gi0] = r0.x;
        else if (d0 == 1) g_npart[z][gi0] = r0.y;
        int d1 = gi0 + 1 - gj;
        if (d1 == 0) g_npart[z][gi0 + 1] = r1.x;
        else if (d1 == 1) g_npart[z][gi0 + 1] = r1.y;
    }
}

// ---------------------------------------------------------------------------
// Kernel 2: triplets. 4 anchors/block, 128 blocks. dist from Gram partials.
// Negatives (rare) compacted via shared atomic; positives stay in registers.
// Last block writes loss = sum / (count + 1e-16) and resets accumulators.
// ---------------------------------------------------------------------------
__global__ __launch_bounds__(256) void k_tri(float* __restrict__ out) {
    __shared__ float    norms[BB];
    __shared__ unsigned labs[BB];
    __shared__ float    nd[BB];
    __shared__ int      nn;
    __shared__ float    wsum[8];
    __shared__ unsigned wcnt[8];

    int tid = threadIdx.x;
    for (int t = tid; t < BB; t += 256) {
        norms[t] = g_npart[0][t] + g_npart[1][t];
        labs[t]  = g_lab[t];
    }
    __syncthreads();

    float    lsum = 0.0f;
    unsigned lcnt = 0u;

    for (int a = 0; a < 4; ++a) {
        int i = blockIdx.x * 4 + a;
        unsigned mi = labs[i];
        float    ni = norms[i];
        if (tid == 0) nn = 0;
        __syncthreads();

        float dv[2];
        int   pf[2];
#pragma unroll
        for (int s = 0; s < 2; ++s) {
            int j = tid + s * 256;
            float G  = g_part[0][i * BB + j] + g_part[1][i * BB + j];
            float sq = ni + norms[j] - 2.0f * G;
            float d  = (sq > 0.0f) ? sqrtf(sq) : 0.0f;
            int pos  = (labs[j] & mi) != 0u;
            dv[s] = d; pf[s] = pos;
            if (!pos) nd[atomicAdd(&nn, 1)] = d;
        }
        __syncthreads();

        int N = nn;
        if (N > 0) {
#pragma unroll
            for (int s = 0; s < 2; ++s) {
                if (pf[s]) {
                    float dj = dv[s];
                    for (int k = 0; k < N; ++k) {
                        float v = dj - nd[k];
                        if (v > 1e-16f) { lsum += v; lcnt++; }
                    }
                }
            }
        }
        __syncthreads();
    }

#pragma unroll
    for (int off = 16; off; off >>= 1) {
        lsum += __shfl_down_sync(0xffffffffu, lsum, off);
        lcnt += __shfl_down_sync(0xffffffffu, lcnt, off);
    }
    int lane = tid & 31, wid = tid >> 5;
    if (lane == 0) { wsum[wid] = lsum; wcnt[wid] = lcnt; }
    __syncthreads();
    if (wid == 0) {
        lsum = (lane < 8) ? wsum[lane] : 0.0f;
        lcnt = (lane < 8) ? wcnt[lane] : 0u;
#pragma unroll
        for (int off = 4; off; off >>= 1) {
            lsum += __shfl_down_sync(0xffffffffu, lsum, off);
            lcnt += __shfl_down_sync(0xffffffffu, lcnt, off);
        }
        if (lane == 0) {
            if (lcnt != 0u || lsum != 0.0f) {
                atomicAdd(&g_sum, lsum);
                atomicAdd(&g_cnt, lcnt);
            }
            __threadfence();
            unsigned prev = atomicAdd(&g_done, 1u);
            if (prev == NTRI - 1) {
                float    s = *((volatile float*)&g_sum);
                unsigned c = *((volatile unsigned*)&g_cnt);
                out[0] = (float)((double)s / ((double)c + 1e-16));
                g_sum = 0.0f; g_cnt = 0u; g_done = 0u;  // reset for replay
            }
        }
    }
}

extern "C" void kernel_launch(void* const* d_in, const int* in_sizes, int n_in,
                              void* d_out, int out_size) {
    const float* src = (const float*)d_in[0];  // (B, D) float32
    const int*   lab = (const int*)d_in[1];    // (B, L) int32

    dim3 grid(BB / TILE, BB / TILE, SPLITS);   // 8 x 8 x 2 = 128 blocks
    k_gram<<<grid, 256>>>(src, lab);
    k_tri<<<NTRI, 256>>>((float*)d_out);
}